// round 1
// baseline (speedup 1.0000x reference)
#include <cuda_runtime.h>
#include <math.h>

#define BATCH 8192
#define PDIM  512
#define DM    256
#define DI    512     // D_INNER
#define DTR   16
#define DS    16
#define ADIM  64
#define XDW   48      // DT_RANK + 2*D_STATE

// ---- static scratch (no cudaMalloc allowed) ----
__device__ float g_X[BATCH * DM];        // after input proj
__device__ float g_XZ[BATCH * 2 * DI];   // in_proj output (u | z)
__device__ float g_U2[BATCH * DI];       // silu(conv(u))
__device__ float g_XD[BATCH * XDW];      // x_dbl: dt|B|C
__device__ float g_DELTA[BATCH * DI];    // softplus(dt @ dt_proj^T + b)
__device__ float g_Y[BATCH * DI];        // gated ssm output
__device__ float g_H[BATCH * DM];        // out_proj output

// Epilogues: 0=none, 1=+bias, 2=softplus(+bias), 3=tanh(+bias), 4=clip(+bias,-5,2)
template <int EPI>
__global__ void __launch_bounds__(256)
gemm_nt(const float* __restrict__ A, int lda,
        const float* __restrict__ W,          // row-major [N, K]
        const float* __restrict__ bias,
        float* __restrict__ C, int ldc,
        int M, int N, int K) {
    const int BM = 64, BN = 64, BK = 16;
    __shared__ float As[BK][BM];
    __shared__ float Ws[BK][BN];

    const int tid = threadIdx.x;            // 256 threads
    const int bm  = blockIdx.x * BM;
    const int bn  = blockIdx.y * BN;
    const int tx  = tid & 15;               // 16 x 16 thread grid
    const int ty  = tid >> 4;

    const int lr = tid >> 2;                // 0..63: row within tile
    const int lk = (tid & 3) * 4;           // k offset: 0,4,8,12

    float acc[4][4];
#pragma unroll
    for (int i = 0; i < 4; i++)
#pragma unroll
        for (int j = 0; j < 4; j++) acc[i][j] = 0.f;

    for (int k0 = 0; k0 < K; k0 += BK) {
        // load A tile (M rows always in-bounds: M % 64 == 0 for all stages)
        float4 a4 = *(const float4*)(A + (size_t)(bm + lr) * lda + k0 + lk);
        As[lk + 0][lr] = a4.x; As[lk + 1][lr] = a4.y;
        As[lk + 2][lr] = a4.z; As[lk + 3][lr] = a4.w;
        // load W tile (guard N)
        float4 w4 = make_float4(0.f, 0.f, 0.f, 0.f);
        int wn = bn + lr;
        if (wn < N) w4 = *(const float4*)(W + (size_t)wn * K + k0 + lk);
        Ws[lk + 0][lr] = w4.x; Ws[lk + 1][lr] = w4.y;
        Ws[lk + 2][lr] = w4.z; Ws[lk + 3][lr] = w4.w;
        __syncthreads();

#pragma unroll
        for (int kk = 0; kk < BK; kk++) {
            float a[4], b[4];
            *(float4*)a = *(const float4*)&As[kk][ty * 4];
            *(float4*)b = *(const float4*)&Ws[kk][tx * 4];
#pragma unroll
            for (int i = 0; i < 4; i++)
#pragma unroll
                for (int j = 0; j < 4; j++) acc[i][j] += a[i] * b[j];
        }
        __syncthreads();
    }

#pragma unroll
    for (int i = 0; i < 4; i++) {
        int row = bm + ty * 4 + i;
#pragma unroll
        for (int j = 0; j < 4; j++) {
            int col = bn + tx * 4 + j;
            if (col < N) {
                float v = acc[i][j];
                if (EPI >= 1) v += bias[col];
                if (EPI == 2) v = (v > 20.f) ? v : log1pf(expf(v));     // softplus
                if (EPI == 3) v = tanhf(v);
                if (EPI == 4) v = fminf(fmaxf(v, -5.f), 2.f);
                C[(size_t)row * ldc + col] = v;
            }
        }
    }
}

// u2 = silu(u * conv_w[c,3] + conv_b[c])   (L=1: conv window is [0,0,0,u])
__global__ void silu_conv_kernel(const float* __restrict__ XZ,
                                 const float* __restrict__ conv_w,
                                 const float* __restrict__ conv_b,
                                 float* __restrict__ U2) {
    int idx = blockIdx.x * blockDim.x + threadIdx.x;
    if (idx >= BATCH * DI) return;
    int c = idx & (DI - 1);
    int b = idx >> 9;
    float u = XZ[(size_t)b * (2 * DI) + c];
    float v = u * conv_w[c * 4 + 3] + conv_b[c];
    U2[idx] = v / (1.f + expf(-v));
}

// y = (delta*u2*(B.C) + Dskip*u2) * silu(z)     (h0 = 0, L = 1 -> scan collapses)
__global__ void __launch_bounds__(256)
ygate_kernel(const float* __restrict__ XZ, const float* __restrict__ U2,
             const float* __restrict__ XD, const float* __restrict__ DELTA,
             const float* __restrict__ Dskip, float* __restrict__ Y) {
    int b = blockIdx.x;
    __shared__ float s_bc;
    int tid = threadIdx.x;
    if (tid < 32) {
        float p = 0.f;
        if (tid < DS) p = XD[b * XDW + DTR + tid] * XD[b * XDW + DTR + DS + tid];
#pragma unroll
        for (int o = 8; o > 0; o >>= 1) p += __shfl_down_sync(0xffffffffu, p, o);
        if (tid == 0) s_bc = p;
    }
    __syncthreads();
    float bc = s_bc;
    for (int d = tid; d < DI; d += 256) {
        float u = U2[(size_t)b * DI + d];
        float z = XZ[(size_t)b * (2 * DI) + DI + d];
        float y = DELTA[(size_t)b * DI + d] * u * bc + Dskip[d] * u;
        Y[(size_t)b * DI + d] = y * (z / (1.f + expf(-z)));
    }
}

extern "C" void kernel_launch(void* const* d_in, const int* in_sizes, int n_in,
                              void* d_out, int out_size) {
    const float* perception = (const float*)d_in[0];
    const float* W_in       = (const float*)d_in[1];
    const float* b_in       = (const float*)d_in[2];
    const float* mu_w       = (const float*)d_in[3];
    const float* mu_b       = (const float*)d_in[4];
    const float* ls_w       = (const float*)d_in[5];
    const float* ls_b       = (const float*)d_in[6];
    const float* in_proj_w  = (const float*)d_in[7];
    const float* conv_w     = (const float*)d_in[8];
    const float* conv_b     = (const float*)d_in[9];
    const float* x_proj_w   = (const float*)d_in[10];
    const float* dt_proj_w  = (const float*)d_in[11];
    const float* dt_proj_b  = (const float*)d_in[12];
    // d_in[13] = A_log (dead: h0 == 0 with L == 1), d_in[14] = Dskip
    const float* Dskip      = (const float*)d_in[14];
    const float* out_proj_w = (const float*)d_in[15];

    float* out = (float*)d_out;             // [mu (8192x64) | log_std (8192x64)]

    float *X, *XZ, *U2, *XD, *DELTA, *Y, *H;
    cudaGetSymbolAddress((void**)&X, g_X);
    cudaGetSymbolAddress((void**)&XZ, g_XZ);
    cudaGetSymbolAddress((void**)&U2, g_U2);
    cudaGetSymbolAddress((void**)&XD, g_XD);
    cudaGetSymbolAddress((void**)&DELTA, g_DELTA);
    cudaGetSymbolAddress((void**)&Y, g_Y);
    cudaGetSymbolAddress((void**)&H, g_H);

    const int MB = BATCH / 64;              // 128 M-tiles

    // 1) X = perception @ W_in^T + b_in        [8192, 256]
    gemm_nt<1><<<dim3(MB, DM / 64), 256>>>(perception, PDIM, W_in, b_in, X, DM,
                                           BATCH, DM, PDIM);
    // 2) XZ = X @ in_proj_w^T                  [8192, 1024]
    gemm_nt<0><<<dim3(MB, (2 * DI) / 64), 256>>>(X, DM, in_proj_w, nullptr, XZ,
                                                 2 * DI, BATCH, 2 * DI, DM);
    // 3) u2 = silu(conv1x(u))                  [8192, 512]
    silu_conv_kernel<<<(BATCH * DI) / 256, 256>>>(XZ, conv_w, conv_b, U2);
    // 4) x_dbl = u2 @ x_proj_w^T               [8192, 48]
    gemm_nt<0><<<dim3(MB, 1), 256>>>(U2, DI, x_proj_w, nullptr, XD, XDW,
                                     BATCH, XDW, DI);
    // 5) delta = softplus(dt @ dt_proj_w^T + dt_proj_b)   [8192, 512]
    gemm_nt<2><<<dim3(MB, DI / 64), 256>>>(XD, XDW, dt_proj_w, dt_proj_b, DELTA,
                                           DI, BATCH, DI, DTR);
    // 6) y = (delta*u2*(B.C) + Dskip*u2) * silu(z)        [8192, 512]
    ygate_kernel<<<BATCH, 256>>>(XZ, U2, XD, DELTA, Dskip, Y);
    // 7) H = y @ out_proj_w^T                  [8192, 256]
    gemm_nt<0><<<dim3(MB, DM / 64), 256>>>(Y, DI, out_proj_w, nullptr, H, DM,
                                           BATCH, DM, DI);
    // 8) mu = tanh(H @ mu_w^T + mu_b)          [8192, 64]
    gemm_nt<3><<<dim3(MB, 1), 256>>>(H, DM, mu_w, mu_b, out, ADIM,
                                     BATCH, ADIM, DM);
    // 9) log_std = clip(H @ ls_w^T + ls_b)     [8192, 64]
    gemm_nt<4><<<dim3(MB, 1), 256>>>(H, DM, ls_w, ls_b, out + BATCH * ADIM, ADIM,
                                     BATCH, ADIM, DM);
    (void)in_sizes; (void)n_in; (void)out_size;
}

// round 3
// speedup vs baseline: 2.2005x; 2.2005x over previous
#include <cuda_runtime.h>
#include <math.h>
#include <stdint.h>

#define BATCH 8192
#define PDIM  512
#define DM    256
#define DI    512
#define DTR   16
#define DS    16
#define ADIM  64
#define XDW   48

// ---- static scratch ----
__device__ float g_X[BATCH * DM];
__device__ float g_U2[BATCH * DI];
__device__ float g_G[BATCH * DI];      // silu(z)
__device__ float g_XD[BATCH * XDW];
__device__ float g_Y[BATCH * DI];
__device__ float g_H[BATCH * DM];

__device__ __forceinline__ float cvt_tf32(float x) {
    uint32_t u;
    asm("cvt.rna.tf32.f32 %0, %1;" : "=r"(u) : "f"(x));
    return __uint_as_float(u);
}

__device__ __forceinline__ void mma_tf32(float* c, const uint32_t* a,
                                         uint32_t b0, uint32_t b1) {
    asm volatile(
        "mma.sync.aligned.m16n8k8.row.col.f32.tf32.tf32.f32 "
        "{%0,%1,%2,%3},{%4,%5,%6,%7},{%8,%9},{%0,%1,%2,%3};"
        : "+f"(c[0]), "+f"(c[1]), "+f"(c[2]), "+f"(c[3])
        : "r"(a[0]), "r"(a[1]), "r"(a[2]), "r"(a[3]), "r"(b0), "r"(b1));
}

__device__ __forceinline__ float sigmoidf_(float x) { return 1.f / (1.f + expf(-x)); }
__device__ __forceinline__ float softplusf_(float x) {
    return (x > 20.f) ? x : log1pf(expf(x));
}

// C[M,N] = A[M,K] @ W[N,K]^T, tf32 tensor-core, BM=128 BN=64 BK=16, 256 thr.
// EPI: 0 plain (guard col<N), 1 +bias, 2 mamba-in (U2/G split), 3 dual heads
template <int EPI>
__global__ void __launch_bounds__(256)
gemm_tc(const float* __restrict__ A, int lda,
        const float* __restrict__ W, const float* __restrict__ bias,
        float* __restrict__ C, int ldc, int M, int N, int K,
        const float* __restrict__ aux0, const float* __restrict__ aux1,
        float* __restrict__ aux2) {
    const int BM = 128, BN = 64, BK = 16, PAD = 20;
    __shared__ float As[2][BM][PAD];
    __shared__ float Ws[2][BN][PAD];

    const int tid  = threadIdx.x;
    const int lane = tid & 31, wid = tid >> 5;
    const int wm = (wid & 3) * 32, wn = (wid >> 2) * 32;
    const int g = lane >> 2, t = lane & 3;
    const int bm = blockIdx.x * BM;
    const int bn = (EPI == 3) ? 0 : blockIdx.y * BN;

    // head selection for EPI3
    const float* Wp = W;
    const float* bp = bias;
    float* Cp = C;
    if (EPI == 3 && blockIdx.y == 1) { Wp = aux0; bp = aux1; Cp = aux2; }
    if (EPI != 3) { Wp = W; bp = bias; Cp = C; }

    // global-load coordinates
    const int ar0 = tid >> 2;                 // A rows: tid>>2 and +64
    const int ak  = (tid & 3) * 4;
    const int wr  = tid >> 2;                 // W row 0..63
    const int nTiles = K / BK;

    float acc[2][4][4];
#pragma unroll
    for (int i = 0; i < 2; i++)
#pragma unroll
        for (int j = 0; j < 4; j++)
#pragma unroll
            for (int l = 0; l < 4; l++) acc[i][j][l] = 0.f;

    // load tile 0
    {
        float4 a0 = *(const float4*)(A + (size_t)(bm + ar0) * lda + ak);
        float4 a1 = *(const float4*)(A + (size_t)(bm + ar0 + 64) * lda + ak);
        float4 w0 = make_float4(0.f, 0.f, 0.f, 0.f);
        if (bn + wr < N) w0 = *(const float4*)(Wp + (size_t)(bn + wr) * K + ak);
        As[0][ar0][ak + 0] = cvt_tf32(a0.x); As[0][ar0][ak + 1] = cvt_tf32(a0.y);
        As[0][ar0][ak + 2] = cvt_tf32(a0.z); As[0][ar0][ak + 3] = cvt_tf32(a0.w);
        As[0][ar0 + 64][ak + 0] = cvt_tf32(a1.x); As[0][ar0 + 64][ak + 1] = cvt_tf32(a1.y);
        As[0][ar0 + 64][ak + 2] = cvt_tf32(a1.z); As[0][ar0 + 64][ak + 3] = cvt_tf32(a1.w);
        Ws[0][wr][ak + 0] = cvt_tf32(w0.x); Ws[0][wr][ak + 1] = cvt_tf32(w0.y);
        Ws[0][wr][ak + 2] = cvt_tf32(w0.z); Ws[0][wr][ak + 3] = cvt_tf32(w0.w);
    }
    __syncthreads();

    for (int kt = 0; kt < nTiles; kt++) {
        const int cur = kt & 1;
        float4 pa0, pa1, pw0;
        const bool more = (kt + 1 < nTiles);
        if (more) {
            int k0 = (kt + 1) * BK;
            pa0 = *(const float4*)(A + (size_t)(bm + ar0) * lda + k0 + ak);
            pa1 = *(const float4*)(A + (size_t)(bm + ar0 + 64) * lda + k0 + ak);
            pw0 = make_float4(0.f, 0.f, 0.f, 0.f);
            if (bn + wr < N) pw0 = *(const float4*)(Wp + (size_t)(bn + wr) * K + k0 + ak);
        }

#pragma unroll
        for (int ks = 0; ks < 2; ks++) {
            const int kb = ks * 8;
            uint32_t a[2][4];
#pragma unroll
            for (int mt = 0; mt < 2; mt++) {
                int row = wm + mt * 16 + g;
                a[mt][0] = __float_as_uint(As[cur][row][kb + t]);
                a[mt][1] = __float_as_uint(As[cur][row + 8][kb + t]);
                a[mt][2] = __float_as_uint(As[cur][row][kb + t + 4]);
                a[mt][3] = __float_as_uint(As[cur][row + 8][kb + t + 4]);
            }
#pragma unroll
            for (int nt = 0; nt < 4; nt++) {
                int nc = wn + nt * 8 + g;
                uint32_t b0 = __float_as_uint(Ws[cur][nc][kb + t]);
                uint32_t b1 = __float_as_uint(Ws[cur][nc][kb + t + 4]);
                mma_tf32(acc[0][nt], a[0], b0, b1);
                mma_tf32(acc[1][nt], a[1], b0, b1);
            }
        }

        if (more) {
            const int nxt = cur ^ 1;
            As[nxt][ar0][ak + 0] = cvt_tf32(pa0.x); As[nxt][ar0][ak + 1] = cvt_tf32(pa0.y);
            As[nxt][ar0][ak + 2] = cvt_tf32(pa0.z); As[nxt][ar0][ak + 3] = cvt_tf32(pa0.w);
            As[nxt][ar0 + 64][ak + 0] = cvt_tf32(pa1.x); As[nxt][ar0 + 64][ak + 1] = cvt_tf32(pa1.y);
            As[nxt][ar0 + 64][ak + 2] = cvt_tf32(pa1.z); As[nxt][ar0 + 64][ak + 3] = cvt_tf32(pa1.w);
            Ws[nxt][wr][ak + 0] = cvt_tf32(pw0.x); Ws[nxt][wr][ak + 1] = cvt_tf32(pw0.y);
            Ws[nxt][wr][ak + 2] = cvt_tf32(pw0.z); Ws[nxt][wr][ak + 3] = cvt_tf32(pw0.w);
        }
        __syncthreads();
    }

    // epilogue
#pragma unroll
    for (int mt = 0; mt < 2; mt++) {
#pragma unroll
        for (int nt = 0; nt < 4; nt++) {
#pragma unroll
            for (int ci = 0; ci < 4; ci++) {
                int row = bm + wm + mt * 16 + g + ((ci >= 2) ? 8 : 0);
                int col = bn + wn + nt * 8 + t * 2 + (ci & 1);
                float v = acc[mt][nt][ci];
                if (EPI == 0) {
                    if (col < N) C[(size_t)row * ldc + col] = v;
                } else if (EPI == 1) {
                    C[(size_t)row * ldc + col] = v + bias[col];
                } else if (EPI == 2) {
                    // v is xz[row][col] of in_proj. col<512 -> u path, else z path
                    if (col < DI) {
                        float w3 = aux0[col * 4 + 3];
                        float cb = aux1[col];
                        float u = v * w3 + cb;
                        C[(size_t)row * DI + col] = u * sigmoidf_(u);          // U2
                    } else {
                        aux2[(size_t)row * DI + (col - DI)] = v * sigmoidf_(v); // G = silu(z)
                    }
                } else { // EPI == 3
                    float h = v + bp[col];
                    if (blockIdx.y == 0) h = tanhf(h);
                    else                 h = fminf(fmaxf(h, -5.f), 2.f);
                    Cp[(size_t)row * ADIM + col] = h;
                }
            }
        }
    }
}

// Fused: delta = softplus(XD[:, :16] @ dt_proj^T + b); bc = B.C;
//        Y = U2 * (delta*bc + Dskip) * G
#define RB 32
__global__ void __launch_bounds__(256)
delta_ygate(const float* __restrict__ XD, const float* __restrict__ dtw,
            const float* __restrict__ dtb, const float* __restrict__ U2,
            const float* __restrict__ G, const float* __restrict__ Dskip,
            float* __restrict__ Y) {
    __shared__ float sXD[RB][XDW];
    __shared__ float sbc[RB];
    const int tid = threadIdx.x;
    const int r0 = blockIdx.x * RB;

    for (int i = tid; i < RB * 12; i += 256) {
        int r = i / 12, c4 = (i % 12) * 4;
        *(float4*)&sXD[r][c4] = *(const float4*)&XD[(size_t)(r0 + r) * XDW + c4];
    }
    __syncthreads();
    if (tid < RB) {
        float s = 0.f;
#pragma unroll
        for (int k = 0; k < DS; k++) s += sXD[tid][DTR + k] * sXD[tid][DTR + DS + k];
        sbc[tid] = s;
    }

    const int c0 = tid, c1 = tid + 256;
    float w0[DTR], w1[DTR];
#pragma unroll
    for (int k = 0; k < DTR; k++) { w0[k] = dtw[c0 * DTR + k]; w1[k] = dtw[c1 * DTR + k]; }
    const float b0v = dtb[c0], b1v = dtb[c1];
    const float d0 = Dskip[c0], d1 = Dskip[c1];
    __syncthreads();

    for (int r = 0; r < RB; r++) {
        float acc0 = b0v, acc1 = b1v;
#pragma unroll
        for (int k = 0; k < DTR; k++) {
            float x = sXD[r][k];
            acc0 += w0[k] * x;
            acc1 += w1[k] * x;
        }
        float bc = sbc[r];
        float de0 = softplusf_(acc0), de1 = softplusf_(acc1);
        size_t base = (size_t)(r0 + r) * DI;
        float u0 = U2[base + c0], u1 = U2[base + c1];
        float gg0 = G[base + c0], gg1 = G[base + c1];
        Y[base + c0] = u0 * (de0 * bc + d0) * gg0;
        Y[base + c1] = u1 * (de1 * bc + d1) * gg1;
    }
}

extern "C" void kernel_launch(void* const* d_in, const int* in_sizes, int n_in,
                              void* d_out, int out_size) {
    const float* perception = (const float*)d_in[0];
    const float* W_in       = (const float*)d_in[1];
    const float* b_in       = (const float*)d_in[2];
    const float* mu_w       = (const float*)d_in[3];
    const float* mu_b       = (const float*)d_in[4];
    const float* ls_w       = (const float*)d_in[5];
    const float* ls_b       = (const float*)d_in[6];
    const float* in_proj_w  = (const float*)d_in[7];
    const float* conv_w     = (const float*)d_in[8];
    const float* conv_b     = (const float*)d_in[9];
    const float* x_proj_w   = (const float*)d_in[10];
    const float* dt_proj_w  = (const float*)d_in[11];
    const float* dt_proj_b  = (const float*)d_in[12];
    const float* Dskip      = (const float*)d_in[14];
    const float* out_proj_w = (const float*)d_in[15];

    float* out = (float*)d_out;

    float *X, *U2, *G, *XD, *Y, *H;
    cudaGetSymbolAddress((void**)&X, g_X);
    cudaGetSymbolAddress((void**)&U2, g_U2);
    cudaGetSymbolAddress((void**)&G, g_G);
    cudaGetSymbolAddress((void**)&XD, g_XD);
    cudaGetSymbolAddress((void**)&Y, g_Y);
    cudaGetSymbolAddress((void**)&H, g_H);

    const int MB = BATCH / 128;   // 64

    // 1) X = perc @ W_in^T + b_in            [8192,256] K=512
    gemm_tc<1><<<dim3(MB, DM / 64), 256>>>(perception, PDIM, W_in, b_in, X, DM,
                                           BATCH, DM, PDIM, nullptr, nullptr, nullptr);
    // 2) in_proj + silu-conv + silu(z)       [8192,1024] K=256 -> U2, G
    gemm_tc<2><<<dim3(MB, (2 * DI) / 64), 256>>>(X, DM, in_proj_w, nullptr, U2, DI,
                                                 BATCH, 2 * DI, DM, conv_w, conv_b, G);
    // 3) XD = U2 @ x_proj^T                  [8192,48] K=512
    gemm_tc<0><<<dim3(MB, 1), 256>>>(U2, DI, x_proj_w, nullptr, XD, XDW,
                                     BATCH, XDW, DI, nullptr, nullptr, nullptr);
    // 4) delta + bc + gate -> Y              [8192,512]
    delta_ygate<<<BATCH / RB, 256>>>(XD, dt_proj_w, dt_proj_b, U2, G, Dskip, Y);
    // 5) H = Y @ out_proj^T                  [8192,256] K=512
    gemm_tc<0><<<dim3(MB, DM / 64), 256>>>(Y, DI, out_proj_w, nullptr, H, DM,
                                           BATCH, DM, DI, nullptr, nullptr, nullptr);
    // 6) heads: mu (by=0) | log_std (by=1)   [8192,64] K=256
    gemm_tc<3><<<dim3(MB, 2), 256>>>(H, DM, mu_w, mu_b, out, ADIM,
                                     BATCH, ADIM, DM, ls_w, ls_b, out + BATCH * ADIM);
    (void)in_sizes; (void)n_in; (void)out_size;
}